// round 1
// baseline (speedup 1.0000x reference)
#include <cuda_runtime.h>

#define MM 50000
#define EE 800000
#define KK 512
#define NN 128

// Scratch (allocation-free rule: __device__ globals)
__device__ float g_x[(size_t)MM * NN];     // feat @ W, 25.6 MB (L2-resident)
__device__ int   g_rowptr[MM + 1];

// ---------------- packed f32x2 helpers (sm_100+/sm_103a) ----------------
__device__ __forceinline__ unsigned long long pk(float lo, float hi) {
    unsigned long long r;
    asm("mov.b64 %0, {%1, %2};" : "=l"(r) : "f"(lo), "f"(hi));
    return r;
}
__device__ __forceinline__ void upk(unsigned long long v, float &lo, float &hi) {
    asm("mov.b64 {%0, %1}, %2;" : "=f"(lo), "=f"(hi) : "l"(v));
}
__device__ __forceinline__ unsigned long long fma2(unsigned long long a,
                                                   unsigned long long b,
                                                   unsigned long long c) {
    unsigned long long d;
    asm("fma.rn.f32x2 %0, %1, %2, %3;" : "=l"(d) : "l"(a), "l"(b), "l"(c));
    return d;
}

// ---------------- GEMM: g_x = feat[M,K] @ W[K,N] (fp32) ----------------
#define BM 64
#define BK 32

__global__ __launch_bounds__(256)
void gemm_kernel(const float* __restrict__ A, const float* __restrict__ B) {
    __shared__ float As[BM][BK + 1];   // pad -> conflict-free k-reads
    __shared__ float Bs[BK][NN];

    const int tid = threadIdx.x;
    const int m0  = blockIdx.x * BM;
    const int tx  = tid & 15;          // n-group: covers n = tx*4..+3 and 64+tx*4..+3
    const int ty  = tid >> 4;          // m-group: covers m = ty*4..+3

    unsigned long long c2[4][4];
    #pragma unroll
    for (int i = 0; i < 4; i++)
        #pragma unroll
        for (int j = 0; j < 4; j++) c2[i][j] = 0ull;

    const int ar = tid >> 3;           // 0..31  (A tile row)
    const int ac = (tid & 7) * 4;      // 0..28  (A tile col, float4)
    const int br = tid >> 5;           // 0..7   (B tile row)
    const int bc = (tid & 31) * 4;     // 0..124 (B tile col, float4)

    for (int kt = 0; kt < KK; kt += BK) {
        // Load A tile (64 x 32), guard tail block, zero-fill OOB rows
        #pragma unroll
        for (int h = 0; h < 2; h++) {
            const int r  = ar + h * 32;
            const int gm = m0 + r;
            float4 v = make_float4(0.f, 0.f, 0.f, 0.f);
            if (gm < MM) v = *(const float4*)(A + (size_t)gm * KK + kt + ac);
            As[r][ac + 0] = v.x; As[r][ac + 1] = v.y;
            As[r][ac + 2] = v.z; As[r][ac + 3] = v.w;
        }
        // Load B tile (32 x 128) — W is tiny (256 KB), stays in L2
        #pragma unroll
        for (int h = 0; h < 4; h++) {
            const int r = br + h * 8;
            *(float4*)&Bs[r][bc] = *(const float4*)(B + (size_t)(kt + r) * NN + bc);
        }
        __syncthreads();

        #pragma unroll
        for (int kk = 0; kk < BK; kk++) {
            unsigned long long av[4], bv[4];
            float4 b0 = *(const float4*)&Bs[kk][tx * 4];
            float4 b1 = *(const float4*)&Bs[kk][64 + tx * 4];
            bv[0] = pk(b0.x, b0.y); bv[1] = pk(b0.z, b0.w);
            bv[2] = pk(b1.x, b1.y); bv[3] = pk(b1.z, b1.w);
            #pragma unroll
            for (int i = 0; i < 4; i++) {
                const float a = As[ty * 4 + i][kk];
                av[i] = pk(a, a);
            }
            #pragma unroll
            for (int i = 0; i < 4; i++)
                #pragma unroll
                for (int j = 0; j < 4; j++)
                    c2[i][j] = fma2(av[i], bv[j], c2[i][j]);
        }
        __syncthreads();
    }

    // Store C (guard tail block)
    #pragma unroll
    for (int i = 0; i < 4; i++) {
        const int gm = m0 + ty * 4 + i;
        if (gm >= MM) continue;
        float4 v;
        upk(c2[i][0], v.x, v.y); upk(c2[i][1], v.z, v.w);
        *(float4*)(g_x + (size_t)gm * NN + tx * 4) = v;
        upk(c2[i][2], v.x, v.y); upk(c2[i][3], v.z, v.w);
        *(float4*)(g_x + (size_t)gm * NN + 64 + tx * 4) = v;
    }
}

// ---------------- row_ptr via binary search (rows are sorted) ----------------
__global__ void rowptr_kernel(const int* __restrict__ rows) {
    const int i = blockIdx.x * blockDim.x + threadIdx.x;
    if (i > MM) return;
    int lo = 0, hi = EE;
    while (lo < hi) {
        const int mid = (lo + hi) >> 1;
        if (rows[mid] < i) lo = mid + 1; else hi = mid;
    }
    g_rowptr[i] = lo;   // first edge index with rows[e] >= i
}

// ---------------- SpMM + multispike: one block per output row ----------------
__global__ __launch_bounds__(128)
void spmm_kernel(const int* __restrict__ cols, const float* __restrict__ ew,
                 float* __restrict__ out) {
    const int row = blockIdx.x;
    const int f   = threadIdx.x;
    const int start = g_rowptr[row];
    const int end   = g_rowptr[row + 1];

    __shared__ int   s_c[128];
    __shared__ float s_w[128];

    float a0 = 0.f, a1 = 0.f, a2 = 0.f, a3 = 0.f;

    for (int base = start; base < end; base += 128) {
        const int n = min(128, end - base);
        __syncthreads();
        if (f < n) { s_c[f] = cols[base + f]; s_w[f] = ew[base + f]; }
        __syncthreads();

        int e = 0;
        // 4 independent accumulators -> MLP=4 on the L2 gather chain
        for (; e + 4 <= n; e += 4) {
            a0 = fmaf(s_w[e + 0], g_x[(size_t)s_c[e + 0] * NN + f], a0);
            a1 = fmaf(s_w[e + 1], g_x[(size_t)s_c[e + 1] * NN + f], a1);
            a2 = fmaf(s_w[e + 2], g_x[(size_t)s_c[e + 2] * NN + f], a2);
            a3 = fmaf(s_w[e + 3], g_x[(size_t)s_c[e + 3] * NN + f], a3);
        }
        for (; e < n; e++)
            a0 = fmaf(s_w[e], g_x[(size_t)s_c[e] * NN + f], a0);
    }

    const float a = (a0 + a1) + (a2 + a3);
    // multispike: floor(clamp(4x,0,4)+0.5)/4
    const float y = floorf(fminf(fmaxf(4.0f * a, 0.0f), 4.0f) + 0.5f);
    out[(size_t)row * NN + f] = y * 0.25f;
}

// ---------------- launch ----------------
extern "C" void kernel_launch(void* const* d_in, const int* in_sizes, int n_in,
                              void* d_out, int out_size) {
    const float* feat   = (const float*)d_in[0];
    const float* weight = (const float*)d_in[1];
    const int*   rows   = (const int*)d_in[2];
    const int*   cols   = (const int*)d_in[3];
    const float* ew     = (const float*)d_in[4];
    float* out = (float*)d_out;

    gemm_kernel<<<(MM + BM - 1) / BM, 256>>>(feat, weight);
    rowptr_kernel<<<(MM + 1 + 255) / 256, 256>>>(rows);
    spmm_kernel<<<MM, 128>>>(cols, ew, out);
}

// round 3
// speedup vs baseline: 1.2937x; 1.2937x over previous
#include <cuda_runtime.h>
#include <cuda_bf16.h>
#include <cstdint>

#define MM 50000
#define EE 800000
#define KK 512
#define NN 128

// ---------------- device scratch (allocation-free rule) ----------------
__device__ float g_x[(size_t)MM * NN];                 // feat @ W (25.6 MB, L2-resident)
__device__ int   g_rowptr[MM + 1];
__device__ __nv_bfloat16 g_wt0[(size_t)NN * KK];       // W^T bf16 split 0  [n][k]
__device__ __nv_bfloat16 g_wt1[(size_t)NN * KK];       // split 1
__device__ __nv_bfloat16 g_wt2[(size_t)NN * KK];       // split 2

// ---------------- W prep: transpose + 3-way bf16 split ----------------
__global__ void prep_w_kernel(const float* __restrict__ W) {
    const int idx = blockIdx.x * blockDim.x + threadIdx.x;   // over N*K = 65536
    if (idx >= NN * KK) return;
    const int n = idx >> 9;          // / KK
    const int k = idx & (KK - 1);
    const float w = W[(size_t)k * NN + n];
    __nv_bfloat16 h0 = __float2bfloat16_rn(w);
    float r = w - __bfloat162float(h0);
    __nv_bfloat16 h1 = __float2bfloat16_rn(r);
    r -= __bfloat162float(h1);
    __nv_bfloat16 h2 = __float2bfloat16_rn(r);
    g_wt0[idx] = h0; g_wt1[idx] = h1; g_wt2[idx] = h2;
}

// ---------------- fp32 -> 3x bf16 split of a pair, packed for HMMA ----------------
__device__ __forceinline__ void split3_pair(float x0, float x1,
                                            uint32_t &u0, uint32_t &u1, uint32_t &u2) {
    __nv_bfloat16 a0 = __float2bfloat16_rn(x0); float ra = x0 - __bfloat162float(a0);
    __nv_bfloat16 a1 = __float2bfloat16_rn(ra); ra -= __bfloat162float(a1);
    __nv_bfloat16 a2 = __float2bfloat16_rn(ra);
    __nv_bfloat16 b0 = __float2bfloat16_rn(x1); float rb = x1 - __bfloat162float(b0);
    __nv_bfloat16 b1 = __float2bfloat16_rn(rb); rb -= __bfloat162float(b1);
    __nv_bfloat16 b2 = __float2bfloat16_rn(rb);
    u0 = (uint32_t)__bfloat16_as_ushort(a0) | ((uint32_t)__bfloat16_as_ushort(b0) << 16);
    u1 = (uint32_t)__bfloat16_as_ushort(a1) | ((uint32_t)__bfloat16_as_ushort(b1) << 16);
    u2 = (uint32_t)__bfloat16_as_ushort(a2) | ((uint32_t)__bfloat16_as_ushort(b2) << 16);
}

__device__ __forceinline__ void hmma16816(float c[4], const uint32_t a[4],
                                          uint32_t b0, uint32_t b1) {
    asm volatile(
        "mma.sync.aligned.m16n8k16.row.col.f32.bf16.bf16.f32 "
        "{%0,%1,%2,%3}, {%4,%5,%6,%7}, {%8,%9}, {%0,%1,%2,%3};"
        : "+f"(c[0]), "+f"(c[1]), "+f"(c[2]), "+f"(c[3])
        : "r"(a[0]), "r"(a[1]), "r"(a[2]), "r"(a[3]), "r"(b0), "r"(b1));
}

// ---------------- GEMM: g_x = feat @ W via HMMA, 3-split bf16 ----------------
// CTA tile: 128(M) x 128(N=full), K chunks of 32. 256 threads = 8 warps (4x2).
// smem: A splits [3][128][PAD] bf16, B splits [3][128][PAD] bf16 ([n][k] layout).
#define BK 32
#define PAD 40                      // stride 40 el = 80B = 20 banks -> conflict-free frags
#define A_BYTES (3 * 128 * PAD * 2)
#define SMEM_BYTES (2 * A_BYTES)    // 61440
#define NCH (KK / BK)

__global__ void __launch_bounds__(256, 2)
gemm_tc_kernel(const float* __restrict__ A) {
    extern __shared__ char smem[];
    __nv_bfloat16* Asm = (__nv_bfloat16*)smem;                 // [3][128][PAD]
    __nv_bfloat16* Bsm = (__nv_bfloat16*)(smem + A_BYTES);     // [3][128][PAD]

    const int tid    = threadIdx.x;
    const int lane   = tid & 31;
    const int warp   = tid >> 5;
    const int warp_m = warp >> 1;            // 0..3  -> 32 rows each
    const int warp_n = warp & 1;             // 0..1  -> 64 cols each
    const int m0     = blockIdx.x * 128;
    const int tr     = lane >> 2;            // 0..7
    const int tc2    = (lane & 3) * 2;       // 0,2,4,6

    const __nv_bfloat16* wt[3] = { g_wt0, g_wt1, g_wt2 };
    const int ai[6] = {0, 0, 1, 0, 1, 2};
    const int bj[6] = {0, 1, 0, 2, 1, 0};

    float acc[2][8][4];
    #pragma unroll
    for (int i = 0; i < 2; i++)
        #pragma unroll
        for (int j = 0; j < 8; j++)
            #pragma unroll
            for (int q = 0; q < 4; q++) acc[i][j][q] = 0.f;

    for (int ch = 0; ch < NCH; ch++) {
        // ---- A chunk: 128 x 32 fp32 -> 3 bf16 split tiles ----
        #pragma unroll
        for (int it = 0; it < 4; it++) {
            const int idx = tid + it * 256;        // 0..1023 float4s
            const int row = idx >> 3;
            const int c4  = idx & 7;               // float4 within 32 cols
            const int gm  = m0 + row;
            float4 v = make_float4(0.f, 0.f, 0.f, 0.f);
            if (gm < MM) v = *(const float4*)(A + (size_t)gm * KK + ch * BK + c4 * 4);
            uint32_t q0, q1, q2, r0, r1, r2;
            split3_pair(v.x, v.y, q0, q1, q2);
            split3_pair(v.z, v.w, r0, r1, r2);
            const int base = row * PAD + c4 * 4;
            *(uint2*)&Asm[0 * 128 * PAD + base] = make_uint2(q0, r0);
            *(uint2*)&Asm[1 * 128 * PAD + base] = make_uint2(q1, r1);
            *(uint2*)&Asm[2 * 128 * PAD + base] = make_uint2(q2, r2);
        }
        // ---- B chunk: 3 splits x [128 n][32 k] bf16 ----
        #pragma unroll
        for (int s = 0; s < 3; s++) {
            #pragma unroll
            for (int it = 0; it < 2; it++) {
                const int idx = tid + it * 256;    // 0..511 16B-pieces
                const int n   = idx >> 2;
                const int kq  = idx & 3;           // 8-bf16 group
                const float4 v = *(const float4*)(wt[s] + (size_t)n * KK + ch * BK + kq * 8);
                *(float4*)&Bsm[s * 128 * PAD + n * PAD + kq * 8] = v;
            }
        }
        __syncthreads();

        // ---- compute: 2 k16-steps x 6 split-products ----
        #pragma unroll
        for (int ks = 0; ks < 2; ks++) {
            const int k0 = ks * 16;
            #pragma unroll
            for (int p = 0; p < 6; p++) {
                const __nv_bfloat16* Ab = Asm + ai[p] * 128 * PAD;
                const __nv_bfloat16* Bb = Bsm + bj[p] * 128 * PAD;
                uint32_t a[2][4];
                #pragma unroll
                for (int mt = 0; mt < 2; mt++) {
                    const int r = warp_m * 32 + mt * 16 + tr;
                    a[mt][0] = *(const uint32_t*)&Ab[(r    ) * PAD + k0 + tc2    ];
                    a[mt][1] = *(const uint32_t*)&Ab[(r + 8) * PAD + k0 + tc2    ];
                    a[mt][2] = *(const uint32_t*)&Ab[(r    ) * PAD + k0 + tc2 + 8];
                    a[mt][3] = *(const uint32_t*)&Ab[(r + 8) * PAD + k0 + tc2 + 8];
                }
                #pragma unroll
                for (int nt = 0; nt < 8; nt++) {
                    const int n = warp_n * 64 + nt * 8 + tr;
                    const uint32_t b0 = *(const uint32_t*)&Bb[n * PAD + k0 + tc2    ];
                    const uint32_t b1 = *(const uint32_t*)&Bb[n * PAD + k0 + tc2 + 8];
                    hmma16816(acc[0][nt], a[0], b0, b1);
                    hmma16816(acc[1][nt], a[1], b0, b1);
                }
            }
        }
        __syncthreads();
    }

    // ---- epilogue: direct STG.64 of fragment pairs ----
    #pragma unroll
    for (int mt = 0; mt < 2; mt++) {
        const int r = m0 + warp_m * 32 + mt * 16 + tr;
        #pragma unroll
        for (int nt = 0; nt < 8; nt++) {
            const int c = warp_n * 64 + nt * 8 + tc2;
            if (r < MM)
                *(float2*)&g_x[(size_t)r * NN + c] =
                    make_float2(acc[mt][nt][0], acc[mt][nt][1]);
            if (r + 8 < MM)
                *(float2*)&g_x[(size_t)(r + 8) * NN + c] =
                    make_float2(acc[mt][nt][2], acc[mt][nt][3]);
        }
    }
}

// ---------------- row_ptr via binary search (rows sorted) ----------------
__global__ void rowptr_kernel(const int* __restrict__ rows) {
    const int i = blockIdx.x * blockDim.x + threadIdx.x;
    if (i > MM) return;
    int lo = 0, hi = EE;
    while (lo < hi) {
        const int mid = (lo + hi) >> 1;
        if (rows[mid] < i) lo = mid + 1; else hi = mid;
    }
    g_rowptr[i] = lo;
}

// ---------------- SpMM + multispike: warp per row, float4 lanes ----------------
__device__ __forceinline__ float mspike(float a) {
    return floorf(fminf(fmaxf(4.0f * a, 0.0f), 4.0f) + 0.5f) * 0.25f;
}

__global__ __launch_bounds__(256)
void spmm_kernel(const int* __restrict__ cols, const float* __restrict__ ew,
                 float* __restrict__ out) {
    const int wid  = threadIdx.x >> 5;
    const int lane = threadIdx.x & 31;
    const int row  = blockIdx.x * 8 + wid;
    if (row >= MM) return;
    const int s = g_rowptr[row];
    const int e = g_rowptr[row + 1];
    const float4* xb = (const float4*)g_x;

    float4 a0 = make_float4(0.f,0.f,0.f,0.f), a1 = a0, a2 = a0, a3 = a0;
    int i = s;
    for (; i + 4 <= e; i += 4) {
        const int c0 = cols[i], c1 = cols[i+1], c2 = cols[i+2], c3 = cols[i+3];
        const float w0 = ew[i], w1 = ew[i+1], w2 = ew[i+2], w3 = ew[i+3];
        const float4 v0 = xb[c0 * 32 + lane];
        const float4 v1 = xb[c1 * 32 + lane];
        const float4 v2 = xb[c2 * 32 + lane];
        const float4 v3 = xb[c3 * 32 + lane];
        a0.x = fmaf(w0, v0.x, a0.x); a0.y = fmaf(w0, v0.y, a0.y);
        a0.z = fmaf(w0, v0.z, a0.z); a0.w = fmaf(w0, v0.w, a0.w);
        a1.x = fmaf(w1, v1.x, a1.x); a1.y = fmaf(w1, v1.y, a1.y);
        a1.z = fmaf(w1, v1.z, a1.z); a1.w = fmaf(w1, v1.w, a1.w);
        a2.x = fmaf(w2, v2.x, a2.x); a2.y = fmaf(w2, v2.y, a2.y);
        a2.z = fmaf(w2, v2.z, a2.z); a2.w = fmaf(w2, v2.w, a2.w);
        a3.x = fmaf(w3, v3.x, a3.x); a3.y = fmaf(w3, v3.y, a3.y);
        a3.z = fmaf(w3, v3.z, a3.z); a3.w = fmaf(w3, v3.w, a3.w);
    }
    for (; i < e; i++) {
        const int c = cols[i];
        const float w = ew[i];
        const float4 v = xb[c * 32 + lane];
        a0.x = fmaf(w, v.x, a0.x); a0.y = fmaf(w, v.y, a0.y);
        a0.z = fmaf(w, v.z, a0.z); a0.w = fmaf(w, v.w, a0.w);
    }
    float4 t;
    t.x = mspike((a0.x + a1.x) + (a2.x + a3.x));
    t.y = mspike((a0.y + a1.y) + (a2.y + a3.y));
    t.z = mspike((a0.z + a1.z) + (a2.z + a3.z));
    t.w = mspike((a0.w + a1.w) + (a2.w + a3.w));
    ((float4*)out)[(size_t)row * 32 + lane] = t;
}

// ---------------- launch ----------------
extern "C" void kernel_launch(void* const* d_in, const int* in_sizes, int n_in,
                              void* d_out, int out_size) {
    const float* feat   = (const float*)d_in[0];
    const float* weight = (const float*)d_in[1];
    const int*   rows   = (const int*)d_in[2];
    const int*   cols   = (const int*)d_in[3];
    const float* ew     = (const float*)d_in[4];
    float* out = (float*)d_out;

    cudaFuncSetAttribute(gemm_tc_kernel,
                         cudaFuncAttributeMaxDynamicSharedMemorySize, SMEM_BYTES);

    prep_w_kernel<<<(NN * KK + 255) / 256, 256>>>(weight);
    rowptr_kernel<<<(MM + 1 + 255) / 256, 256>>>(rows);
    gemm_tc_kernel<<<(MM + 127) / 128, 256, SMEM_BYTES>>>(feat);
    spmm_kernel<<<(MM + 7) / 8, 256>>>(cols, ew, out);
}